// round 14
// baseline (speedup 1.0000x reference)
#include <cuda_runtime.h>
#include <cuda_fp16.h>
#include <cstdint>

// Problem constants
constexpr int B  = 8;
constexpr int C  = 256;
constexpr int H  = 64;
constexpr int W  = 64;
constexpr int HW = H * W;          // 4096
constexpr int K2 = 9;
constexpr int DG = 4;
constexpr int CG = C / DG;         // 64
constexpr int CK = C * K2;         // 2304  (K order: ck' = (g*9+k)*64 + ci)
constexpr int CKP = 4096;          // padded col row stride (power of 2)
constexpr int GN = 32;
constexpr int CPG = C / GN;        // 8

// Scratch (static device arrays)
__device__ __align__(16) __half g_col[(size_t)B * HW * CKP];  // 268 MB col[b][p][ck'] (padded)
__device__ __align__(16) __half g_A[(size_t)C * CK];          // fp16 weights [m][ck']
__device__ __align__(16) float  g_xt[(size_t)B * HW * C];     // 33.5 MB x_t[b][p][c]
__device__ float g_conv[(size_t)B * C * HW];                  // 33.5 MB conv output
__device__ float g_gsum[B * GN];
__device__ float g_gss[B * GN];

// ---------------------------------------------------------------------------
// PTX helpers (baseline PTX only — toolchain targets compute_103, no tcgen05)
// ---------------------------------------------------------------------------
__device__ __forceinline__ uint32_t smem_u32(const void* p) {
    uint32_t a;
    asm("{ .reg .u64 t; cvta.to.shared.u64 t, %1; cvt.u32.u64 %0, t; }" : "=r"(a) : "l"(p));
    return a;
}
__device__ __forceinline__ void cpa16(uint32_t s, const void* g) {
    asm volatile("cp.async.cg.shared.global [%0], [%1], 16;" :: "r"(s), "l"(g));
}
#define CPA_COMMIT() asm volatile("cp.async.commit_group;" ::: "memory")

__device__ __forceinline__ void ldsm_x4(uint32_t& r0, uint32_t& r1, uint32_t& r2,
                                        uint32_t& r3, uint32_t addr) {
    asm volatile("ldmatrix.sync.aligned.m8n8.x4.shared.b16 {%0,%1,%2,%3}, [%4];"
                 : "=r"(r0), "=r"(r1), "=r"(r2), "=r"(r3) : "r"(addr));
}
__device__ __forceinline__ void mma16816(float* c, const uint32_t* a, const uint32_t* b) {
    asm volatile(
        "mma.sync.aligned.m16n8k16.row.col.f32.f16.f16.f32 "
        "{%0,%1,%2,%3}, {%4,%5,%6,%7}, {%8,%9}, {%0,%1,%2,%3};"
        : "+f"(c[0]), "+f"(c[1]), "+f"(c[2]), "+f"(c[3])
        : "r"(a[0]), "r"(a[1]), "r"(a[2]), "r"(a[3]), "r"(b[0]), "r"(b[1]));
}

// 4-channel bilinear gather from transposed image (base = x_t[b][.][c0])
__device__ __forceinline__ float4 bilinear4(const float* __restrict__ base,
                                            float py, float px) {
    const float y0f = floorf(py);
    const float x0f = floorf(px);
    const float ly = py - y0f;
    const float lx = px - x0f;
    const int iy0 = (int)y0f, ix0 = (int)x0f;
    const int iy1 = iy0 + 1,  ix1 = ix0 + 1;

    const bool vy0 = (iy0 >= 0) && (iy0 <= H - 1);
    const bool vy1 = (iy1 >= 0) && (iy1 <= H - 1);
    const bool vx0 = (ix0 >= 0) && (ix0 <= W - 1);
    const bool vx1 = (ix1 >= 0) && (ix1 <= W - 1);

    const int yc0 = min(max(iy0, 0), H - 1);
    const int yc1 = min(max(iy1, 0), H - 1);
    const int xc0 = min(max(ix0, 0), W - 1);
    const int xc1 = min(max(ix1, 0), W - 1);

    const float w00 = (1.f - ly) * (1.f - lx) * ((vy0 && vx0) ? 1.f : 0.f);
    const float w01 = (1.f - ly) * lx         * ((vy0 && vx1) ? 1.f : 0.f);
    const float w10 = ly * (1.f - lx)         * ((vy1 && vx0) ? 1.f : 0.f);
    const float w11 = ly * lx                 * ((vy1 && vx1) ? 1.f : 0.f);

    const float4 t00 = *(const float4*)(base + (size_t)(yc0 * W + xc0) * C);
    const float4 t01 = *(const float4*)(base + (size_t)(yc0 * W + xc1) * C);
    const float4 t10 = *(const float4*)(base + (size_t)(yc1 * W + xc0) * C);
    const float4 t11 = *(const float4*)(base + (size_t)(yc1 * W + xc1) * C);

    float4 r;
    r.x = w00 * t00.x + w01 * t01.x + w10 * t10.x + w11 * t11.x;
    r.y = w00 * t00.y + w01 * t01.y + w10 * t10.y + w11 * t11.y;
    r.z = w00 * t00.z + w01 * t01.z + w10 * t10.z + w11 * t11.z;
    r.w = w00 * t00.w + w01 * t01.w + w10 * t10.w + w11 * t11.w;
    return r;
}

// ---------------------------------------------------------------------------
// Kernel 0 (merged prep): transpose x -> x_t  AND  weight convert + stat zero
// ---------------------------------------------------------------------------
__global__ void __launch_bounds__(256) prep_kernel(const float* __restrict__ x,
                                                   const float* __restrict__ w)
{
    const int bid = blockIdx.x;
    const int tid = threadIdx.x;

    if (bid < 8192) {
        __shared__ float t[32][33];
        const int b  = bid >> 10;
        const int cB = ((bid >> 7) & 7) * 32;
        const int pB = (bid & 127) * 32;
        const int tx = tid & 31, ty = tid >> 5;   // (32, 8)

        const float* xb = x + (size_t)b * C * HW;
        #pragma unroll
        for (int j = 0; j < 4; j++)
            t[ty + j * 8][tx] = xb[(size_t)(cB + ty + j * 8) * HW + pB + tx];
        __syncthreads();
        float* xtb = g_xt + (size_t)b * HW * C;
        #pragma unroll
        for (int j = 0; j < 4; j++)
            xtb[(size_t)(pB + ty + j * 8) * C + cB + tx] = t[tx][ty + j * 8];
    } else {
        const int bid2 = bid - 8192;              // 0..575
        const int i0 = bid2 * 1024 + tid * 4;     // C*CK = 576*1024 exactly
        const int m   = i0 / CK;
        const int ckp = i0 % CK;
        const int gk  = ckp >> 6;
        const int ci  = ckp & 63;
        const int g   = gk / 9;
        const int k   = gk % 9;
        const float* wp = w + ((size_t)m * C + g * CG + ci) * K2 + k;
        __half hv[4];
        #pragma unroll
        for (int q = 0; q < 4; q++)
            hv[q] = __float2half(wp[(size_t)q * K2]);
        *(uint2*)(g_A + i0) = *(uint2*)hv;

        if (bid2 == 0 && tid < B * GN) {
            g_gsum[tid] = 0.f;
            g_gss[tid]  = 0.f;
        }
    }
}

// ---------------------------------------------------------------------------
// Kernel 1: im2col — dense gather, 8 position-pairs per thread (max MLP)
// col[b][p][gk*64+ci] with row stride CKP=4096.  Grid: (HW/256=16, 36, B)
// ---------------------------------------------------------------------------
__global__ void __launch_bounds__(256) im2col_kernel(
    const float* __restrict__ shp, const float* __restrict__ w_offset)
{
    const int tid = threadIdx.x;
    const int gk  = blockIdx.y;
    const int b   = blockIdx.z;
    const int g   = gk / 9, k = gk % 9;

    const float fki = (float)(k / 3 - 1);
    const float fkj = (float)(k % 3 - 1);

    const int ci4 = (tid & 15) * 4;
    const int t16 = tid >> 4;                 // 0..15
    const float* base = g_xt + (size_t)b * HW * C + g * CG + ci4;
    const float* wo = w_offset + (size_t)gk * 8;
    const float wo0 = wo[0], wo1 = wo[1], wo2 = wo[2], wo3 = wo[3];
    const float wo4 = wo[4], wo5 = wo[5], wo6 = wo[6], wo7 = wo[7];

    const int pblk = blockIdx.x * 256;

    #pragma unroll
    for (int pi = 0; pi < 8; pi++) {
        const int pair = pi * 16 + t16;       // 0..127
        const int pl   = pair * 2;
        const int p0   = pblk + pl;
        const int h    = p0 >> 6;
        const int w0   = p0 & 63;

        const float* sp = shp + (size_t)b * 4 * HW + p0;
        const float2 sA2 = *(const float2*)(sp);
        const float2 sB2 = *(const float2*)(sp + HW);
        const float2 sC2 = *(const float2*)(sp + 2 * HW);
        const float2 sD2 = *(const float2*)(sp + 3 * HW);

        const float dy0 = wo0 * sA2.x + wo1 * sB2.x + wo2 * sC2.x + wo3 * sD2.x;
        const float dy1 = wo0 * sA2.y + wo1 * sB2.y + wo2 * sC2.y + wo3 * sD2.y;
        const float dx0 = wo4 * sA2.x + wo5 * sB2.x + wo6 * sC2.x + wo7 * sD2.x;
        const float dx1 = wo4 * sA2.y + wo5 * sB2.y + wo6 * sC2.y + wo7 * sD2.y;

        const float4 v0 = bilinear4(base, dy0 + fki + h, dx0 + fkj + w0);
        const float4 v1 = bilinear4(base, dy1 + fki + h, dx1 + fkj + w0 + 1.f);

        __half* c0 = g_col + (((size_t)b * HW + p0) << 12) + gk * 64 + ci4;
        {
            __half2 t2[2] = { __floats2half2_rn(v0.x, v0.y),
                              __floats2half2_rn(v0.z, v0.w) };
            *(uint2*)c0 = *(uint2*)t2;
        }
        __half* c1 = c0 + CKP;
        {
            __half2 t2[2] = { __floats2half2_rn(v1.x, v1.y),
                              __floats2half2_rn(v1.z, v1.w) };
            *(uint2*)c1 = *(uint2*)t2;
        }
    }
}

// ---------------------------------------------------------------------------
// Kernel 2: HMMA GEMM + fused GN partial statistics
// BM=256 (all M -> B read ONCE), BN=64, BK=64; 8 warps (4m x 2n), 64x32/warp.
// 2-stage double buffer, XOR-swizzled smem (80 KB), 2 CTAs/SM.
// A: [m][k] K-major. B: [n][k] n-major (non-trans ldsm, fragment remap).
// ---------------------------------------------------------------------------
constexpr int BM = 256, BN = 64, BK = 64;
constexpr int NT = CK / BK;               // 36
constexpr int A_STG = BM * BK;            // 32 KB
constexpr int B_STG = BN * BK;            // 8 KB
constexpr uint32_t GEMM_SMEM = 2 * (A_STG + B_STG) * 2;  // 81920 B

__global__ void __launch_bounds__(256, 2) gemm_kernel()
{
    extern __shared__ __half sm[];
    const uint32_t sA = smem_u32(sm);
    const uint32_t sB = sA + 2 * A_STG * 2;

    const int tid  = threadIdx.x;
    const int lane = tid & 31;
    const int warp = tid >> 5;
    const int n0   = blockIdx.x * BN;
    const int b    = blockIdx.y;
    const int wm   = (warp >> 1) * 64;    // 0,64,128,192
    const int wn   = (warp & 1) * 32;     // 0,32

    auto load_tile = [&](int kt, int s) {
        const __half* ga = g_A + (size_t)kt * BK;
        const uint32_t dA = sA + s * A_STG * 2;
        #pragma unroll
        for (int it = 0; it < 8; it++) {
            int idx = it * 256 + tid;      // 0..2047
            int r = idx >> 3, u = idx & 7;
            cpa16(dA + (uint32_t)(r * 8 + (u ^ (r & 7))) * 16,
                  ga + (size_t)r * CK + u * 8);
        }
        const __half* gb = g_col + (((size_t)b * HW + n0) << 12) + (size_t)kt * BK;
        const uint32_t dB = sB + s * B_STG * 2;
        #pragma unroll
        for (int it = 0; it < 2; it++) {
            int idx = it * 256 + tid;      // 0..511
            int r = idx >> 3, u = idx & 7;
            cpa16(dB + (uint32_t)(r * 8 + (u ^ (r & 7))) * 16,
                  gb + ((size_t)r << 12) + u * 8);
        }
        CPA_COMMIT();
    };

    float acc[4][4][4];
    #pragma unroll
    for (int i = 0; i < 4; i++)
        #pragma unroll
        for (int n = 0; n < 4; n++)
            #pragma unroll
            for (int q = 0; q < 4; q++) acc[i][n][q] = 0.f;

    load_tile(0, 0);

    for (int kt = 0; kt < NT; kt++) {
        const int s = kt & 1;
        if (kt + 1 < NT) {
            load_tile(kt + 1, s ^ 1);
            asm volatile("cp.async.wait_group 1;" ::: "memory");
        } else {
            asm volatile("cp.async.wait_group 0;" ::: "memory");
        }
        __syncthreads();

        const uint32_t aBase = sA + s * A_STG * 2;
        const uint32_t bBase = sB + s * B_STG * 2;

        #pragma unroll
        for (int kk = 0; kk < 4; kk++) {
            uint32_t a[4][4];
            #pragma unroll
            for (int i = 0; i < 4; i++) {
                const int r = wm + i * 16 + (lane & 15);
                const int u = (kk * 2 + (lane >> 4)) ^ (r & 7);
                ldsm_x4(a[i][0], a[i][1], a[i][2], a[i][3],
                        aBase + (uint32_t)(r * 8 + u) * 16);
            }
            uint32_t bb[4][2];
            #pragma unroll
            for (int p = 0; p < 2; p++) {
                const int r = wn + p * 16 + (lane & 15);   // n row
                const int u = (kk * 2 + (lane >> 4)) ^ (r & 7);
                uint32_t r0, r1, r2, r3;
                ldsm_x4(r0, r1, r2, r3, bBase + (uint32_t)(r * 8 + u) * 16);
                bb[2 * p][0] = r0;     bb[2 * p][1] = r2;
                bb[2 * p + 1][0] = r1; bb[2 * p + 1][1] = r3;
            }
            #pragma unroll
            for (int i = 0; i < 4; i++)
                #pragma unroll
                for (int n = 0; n < 4; n++)
                    mma16816(acc[i][n], a[i], bb[n]);
        }
        __syncthreads();
    }

    // ---- Epilogue: write conv + fused GN partial stats --------------------
    #pragma unroll
    for (int i = 0; i < 4; i++) {
        const int ml = wm + i * 16 + (lane >> 2);
        float* row0 = g_conv + ((size_t)b * C + ml) * HW + n0 + wn;
        float* row1 = row0 + (size_t)8 * HW;
        #pragma unroll
        for (int n = 0; n < 4; n++) {
            const int col = n * 8 + (lane & 3) * 2;
            *(float2*)(row0 + col) = make_float2(acc[i][n][0], acc[i][n][1]);
            *(float2*)(row1 + col) = make_float2(acc[i][n][2], acc[i][n][3]);
        }
    }

    __syncthreads();
    float* part = (float*)sm;              // [32 groups][sum,ss]
    if (tid < 64) part[tid] = 0.f;
    __syncthreads();

    #pragma unroll
    for (int i = 0; i < 4; i++) {
        float s0 = 0.f, q0 = 0.f, s1 = 0.f, q1 = 0.f;
        #pragma unroll
        for (int n = 0; n < 4; n++) {
            s0 += acc[i][n][0] + acc[i][n][1];
            q0 += acc[i][n][0] * acc[i][n][0] + acc[i][n][1] * acc[i][n][1];
            s1 += acc[i][n][2] + acc[i][n][3];
            q1 += acc[i][n][2] * acc[i][n][2] + acc[i][n][3] * acc[i][n][3];
        }
        #pragma unroll
        for (int o = 1; o < 4; o <<= 1) {
            s0 += __shfl_xor_sync(0xffffffff, s0, o);
            q0 += __shfl_xor_sync(0xffffffff, q0, o);
            s1 += __shfl_xor_sync(0xffffffff, s1, o);
            q1 += __shfl_xor_sync(0xffffffff, q1, o);
        }
        if ((lane & 3) == 0) {
            const int ml = wm + i * 16 + (lane >> 2);
            atomicAdd(&part[(ml >> 3) * 2],           s0);
            atomicAdd(&part[(ml >> 3) * 2 + 1],       q0);
            atomicAdd(&part[((ml + 8) >> 3) * 2],     s1);
            atomicAdd(&part[((ml + 8) >> 3) * 2 + 1], q1);
        }
    }
    __syncthreads();
    if (tid < 32) {
        atomicAdd(&g_gsum[b * GN + tid], part[tid * 2]);
        atomicAdd(&g_gss[b * GN + tid],  part[tid * 2 + 1]);
    }
}

// ---------------------------------------------------------------------------
// Kernel 3: normalize + affine + ReLU (stats finalized inline)
// ---------------------------------------------------------------------------
__global__ void gn_norm_kernel(const float* __restrict__ gamma,
                               const float* __restrict__ beta,
                               float* __restrict__ out)
{
    const size_t base = (size_t)blockIdx.x * 1024;
    const int c  = (int)((base >> 12) & 255);
    const int b  = (int)(base >> 20);
    const int gi = b * GN + (c >> 3);

    const float inv_n = 1.f / (float)(CPG * HW);
    const float mu  = g_gsum[gi] * inv_n;
    const float var = g_gss[gi] * inv_n - mu * mu;
    const float rs  = rsqrtf(var + 1e-5f);
    const float ga  = gamma[c] * rs;
    const float be  = beta[c] - mu * ga;

    const size_t i = base + threadIdx.x * 4;
    float4 v = *(const float4*)(g_conv + i);
    v.x = fmaxf(v.x * ga + be, 0.f);
    v.y = fmaxf(v.y * ga + be, 0.f);
    v.z = fmaxf(v.z * ga + be, 0.f);
    v.w = fmaxf(v.w * ga + be, 0.f);
    *(float4*)(out + i) = v;
}

// ---------------------------------------------------------------------------
extern "C" void kernel_launch(void* const* d_in, const int* in_sizes, int n_in,
                              void* d_out, int out_size)
{
    const float* x        = (const float*)d_in[0];
    const float* shp      = (const float*)d_in[1];
    const float* w_offset = (const float*)d_in[2];
    const float* w_deform = (const float*)d_in[3];
    const float* gamma    = (const float*)d_in[4];
    const float* beta     = (const float*)d_in[5];
    float* out = (float*)d_out;

    static bool attr_set = false;
    if (!attr_set) {
        cudaFuncSetAttribute(gemm_kernel, cudaFuncAttributeMaxDynamicSharedMemorySize,
                             GEMM_SMEM);
        attr_set = true;
    }

    prep_kernel<<<8768, 256>>>(x, w_deform);

    dim3 g1(HW / 256, DG * K2, B);         // (16, 36, 8)
    im2col_kernel<<<g1, 256>>>(shp, w_offset);

    dim3 g2(HW / BN, B);                   // (64, 8)
    gemm_kernel<<<g2, 256, GEMM_SMEM>>>();

    gn_norm_kernel<<<(unsigned)((size_t)B * C * HW / 1024), 256>>>(gamma, beta, out);
}

// round 15
// speedup vs baseline: 1.0500x; 1.0500x over previous
#include <cuda_runtime.h>
#include <cuda_fp16.h>
#include <cstdint>

// Problem constants
constexpr int B  = 8;
constexpr int C  = 256;
constexpr int H  = 64;
constexpr int W  = 64;
constexpr int HW = H * W;          // 4096
constexpr int K2 = 9;
constexpr int DG = 4;
constexpr int CG = C / DG;         // 64
constexpr int CK = C * K2;         // 2304  (K order: ck' = (g*9+k)*64 + ci)
constexpr int CKP = 4096;          // padded col row stride (power of 2)
constexpr int GN = 32;
constexpr int CPG = C / GN;        // 8

// Scratch (static device arrays)
__device__ __align__(16) __half g_col[(size_t)B * HW * CKP];  // 268 MB col[b][p][ck'] (padded)
__device__ __align__(16) __half g_A[(size_t)C * CK];          // fp16 weights [m][ck']
__device__ __align__(16) float  g_xt[(size_t)B * HW * C];     // 33.5 MB x_t[b][p][c]
__device__ float g_conv[(size_t)B * C * HW];                  // 33.5 MB conv output
__device__ float g_gsum[B * GN];
__device__ float g_gss[B * GN];

// ---------------------------------------------------------------------------
// PTX helpers (baseline PTX only — toolchain targets compute_103, no tcgen05)
// ---------------------------------------------------------------------------
__device__ __forceinline__ uint32_t smem_u32(const void* p) {
    uint32_t a;
    asm("{ .reg .u64 t; cvta.to.shared.u64 t, %1; cvt.u32.u64 %0, t; }" : "=r"(a) : "l"(p));
    return a;
}
__device__ __forceinline__ void cpa16(uint32_t s, const void* g) {
    asm volatile("cp.async.cg.shared.global [%0], [%1], 16;" :: "r"(s), "l"(g));
}
#define CPA_COMMIT() asm volatile("cp.async.commit_group;" ::: "memory")

__device__ __forceinline__ void ldsm_x4(uint32_t& r0, uint32_t& r1, uint32_t& r2,
                                        uint32_t& r3, uint32_t addr) {
    asm volatile("ldmatrix.sync.aligned.m8n8.x4.shared.b16 {%0,%1,%2,%3}, [%4];"
                 : "=r"(r0), "=r"(r1), "=r"(r2), "=r"(r3) : "r"(addr));
}
__device__ __forceinline__ void mma16816(float* c, const uint32_t* a, const uint32_t* b) {
    asm volatile(
        "mma.sync.aligned.m16n8k16.row.col.f32.f16.f16.f32 "
        "{%0,%1,%2,%3}, {%4,%5,%6,%7}, {%8,%9}, {%0,%1,%2,%3};"
        : "+f"(c[0]), "+f"(c[1]), "+f"(c[2]), "+f"(c[3])
        : "r"(a[0]), "r"(a[1]), "r"(a[2]), "r"(a[3]), "r"(b[0]), "r"(b[1]));
}

// 4-channel bilinear gather from transposed image (base = x_t[b][.][c0])
__device__ __forceinline__ float4 bilinear4(const float* __restrict__ base,
                                            float py, float px) {
    const float y0f = floorf(py);
    const float x0f = floorf(px);
    const float ly = py - y0f;
    const float lx = px - x0f;
    const int iy0 = (int)y0f, ix0 = (int)x0f;
    const int iy1 = iy0 + 1,  ix1 = ix0 + 1;

    const bool vy0 = (iy0 >= 0) && (iy0 <= H - 1);
    const bool vy1 = (iy1 >= 0) && (iy1 <= H - 1);
    const bool vx0 = (ix0 >= 0) && (ix0 <= W - 1);
    const bool vx1 = (ix1 >= 0) && (ix1 <= W - 1);

    const int yc0 = min(max(iy0, 0), H - 1);
    const int yc1 = min(max(iy1, 0), H - 1);
    const int xc0 = min(max(ix0, 0), W - 1);
    const int xc1 = min(max(ix1, 0), W - 1);

    const float w00 = (1.f - ly) * (1.f - lx) * ((vy0 && vx0) ? 1.f : 0.f);
    const float w01 = (1.f - ly) * lx         * ((vy0 && vx1) ? 1.f : 0.f);
    const float w10 = ly * (1.f - lx)         * ((vy1 && vx0) ? 1.f : 0.f);
    const float w11 = ly * lx                 * ((vy1 && vx1) ? 1.f : 0.f);

    const float4 t00 = *(const float4*)(base + (size_t)(yc0 * W + xc0) * C);
    const float4 t01 = *(const float4*)(base + (size_t)(yc0 * W + xc1) * C);
    const float4 t10 = *(const float4*)(base + (size_t)(yc1 * W + xc0) * C);
    const float4 t11 = *(const float4*)(base + (size_t)(yc1 * W + xc1) * C);

    float4 r;
    r.x = w00 * t00.x + w01 * t01.x + w10 * t10.x + w11 * t11.x;
    r.y = w00 * t00.y + w01 * t01.y + w10 * t10.y + w11 * t11.y;
    r.z = w00 * t00.z + w01 * t01.z + w10 * t10.z + w11 * t11.z;
    r.w = w00 * t00.w + w01 * t01.w + w10 * t10.w + w11 * t11.w;
    return r;
}

// ---------------------------------------------------------------------------
// Kernel 0 (merged prep): transpose x -> x_t  AND  weight convert + stat zero
// ---------------------------------------------------------------------------
__global__ void __launch_bounds__(256) prep_kernel(const float* __restrict__ x,
                                                   const float* __restrict__ w)
{
    const int bid = blockIdx.x;
    const int tid = threadIdx.x;

    if (bid < 8192) {
        __shared__ float t[32][33];
        const int b  = bid >> 10;
        const int cB = ((bid >> 7) & 7) * 32;
        const int pB = (bid & 127) * 32;
        const int tx = tid & 31, ty = tid >> 5;   // (32, 8)

        const float* xb = x + (size_t)b * C * HW;
        #pragma unroll
        for (int j = 0; j < 4; j++)
            t[ty + j * 8][tx] = xb[(size_t)(cB + ty + j * 8) * HW + pB + tx];
        __syncthreads();
        float* xtb = g_xt + (size_t)b * HW * C;
        #pragma unroll
        for (int j = 0; j < 4; j++)
            xtb[(size_t)(pB + ty + j * 8) * C + cB + tx] = t[tx][ty + j * 8];
    } else {
        const int bid2 = bid - 8192;              // 0..575
        const int i0 = bid2 * 1024 + tid * 4;     // C*CK = 576*1024 exactly
        const int m   = i0 / CK;
        const int ckp = i0 % CK;
        const int gk  = ckp >> 6;
        const int ci  = ckp & 63;
        const int g   = gk / 9;
        const int k   = gk % 9;
        const float* wp = w + ((size_t)m * C + g * CG + ci) * K2 + k;
        __half hv[4];
        #pragma unroll
        for (int q = 0; q < 4; q++)
            hv[q] = __float2half(wp[(size_t)q * K2]);
        *(uint2*)(g_A + i0) = *(uint2*)hv;

        if (bid2 == 0 && tid < B * GN) {
            g_gsum[tid] = 0.f;
            g_gss[tid]  = 0.f;
        }
    }
}

// ---------------------------------------------------------------------------
// Kernel 1: im2col — dense gather, 16 position-pairs per thread (max MLP)
// col[b][p][gk*64+ci] with row stride CKP=4096.  Grid: (HW/512=8, 36, B)
// ---------------------------------------------------------------------------
__global__ void __launch_bounds__(256) im2col_kernel(
    const float* __restrict__ shp, const float* __restrict__ w_offset)
{
    const int tid = threadIdx.x;
    const int gk  = blockIdx.y;
    const int b   = blockIdx.z;
    const int g   = gk / 9, k = gk % 9;

    const float fki = (float)(k / 3 - 1);
    const float fkj = (float)(k % 3 - 1);

    const int ci4 = (tid & 15) * 4;
    const int t16 = tid >> 4;                 // 0..15
    const float* base = g_xt + (size_t)b * HW * C + g * CG + ci4;
    const float* wo = w_offset + (size_t)gk * 8;
    const float wo0 = wo[0], wo1 = wo[1], wo2 = wo[2], wo3 = wo[3];
    const float wo4 = wo[4], wo5 = wo[5], wo6 = wo[6], wo7 = wo[7];

    const int pblk = blockIdx.x * 512;        // 512 positions per block

    #pragma unroll
    for (int pi = 0; pi < 16; pi++) {
        const int pair = pi * 16 + t16;       // 0..255
        const int pl   = pair * 2;
        const int p0   = pblk + pl;
        const int h    = p0 >> 6;
        const int w0   = p0 & 63;

        const float* sp = shp + (size_t)b * 4 * HW + p0;
        const float2 sA2 = *(const float2*)(sp);
        const float2 sB2 = *(const float2*)(sp + HW);
        const float2 sC2 = *(const float2*)(sp + 2 * HW);
        const float2 sD2 = *(const float2*)(sp + 3 * HW);

        const float dy0 = wo0 * sA2.x + wo1 * sB2.x + wo2 * sC2.x + wo3 * sD2.x;
        const float dy1 = wo0 * sA2.y + wo1 * sB2.y + wo2 * sC2.y + wo3 * sD2.y;
        const float dx0 = wo4 * sA2.x + wo5 * sB2.x + wo6 * sC2.x + wo7 * sD2.x;
        const float dx1 = wo4 * sA2.y + wo5 * sB2.y + wo6 * sC2.y + wo7 * sD2.y;

        const float4 v0 = bilinear4(base, dy0 + fki + h, dx0 + fkj + w0);
        const float4 v1 = bilinear4(base, dy1 + fki + h, dx1 + fkj + w0 + 1.f);

        __half* c0 = g_col + (((size_t)b * HW + p0) << 12) + gk * 64 + ci4;
        {
            __half2 t2[2] = { __floats2half2_rn(v0.x, v0.y),
                              __floats2half2_rn(v0.z, v0.w) };
            *(uint2*)c0 = *(uint2*)t2;
        }
        __half* c1 = c0 + CKP;
        {
            __half2 t2[2] = { __floats2half2_rn(v1.x, v1.y),
                              __floats2half2_rn(v1.z, v1.w) };
            *(uint2*)c1 = *(uint2*)t2;
        }
    }
}

// ---------------------------------------------------------------------------
// Kernel 2: HMMA GEMM + fused GN partial statistics  (round-13 config —
// best measured on the p-major layout: 125 us)
// BM=128, BN=64, BK=64; 3-stage cp.async pipeline, XOR-swizzled smem,
// 3 CTAs/SM. A: [m][k] K-major. B: [n][k] n-major (non-trans ldsm, remap).
// ---------------------------------------------------------------------------
constexpr int BM = 128, BN = 64, BK = 64;
constexpr int NT = CK / BK;               // 36
constexpr int NSTG = 3;
constexpr int A_STG = BM * BK;            // 16 KB
constexpr int B_STG = BN * BK;            // 8 KB
constexpr uint32_t GEMM_SMEM = NSTG * (A_STG + B_STG) * 2;  // 73728 B

__global__ void __launch_bounds__(256, 3) gemm_kernel()
{
    extern __shared__ __half sm[];
    const uint32_t sA = smem_u32(sm);
    const uint32_t sB = sA + NSTG * A_STG * 2;

    const int tid  = threadIdx.x;
    const int lane = tid & 31;
    const int warp = tid >> 5;
    const int n0   = blockIdx.x * BN;
    const int my   = blockIdx.y;          // m-tile (0/1)
    const int b    = blockIdx.z;
    const int wm   = (warp >> 1) * 32;
    const int wn   = (warp & 1) * 32;

    auto load_tile = [&](int kt, int s) {
        const __half* ga = g_A + ((size_t)my * BM) * CK + (size_t)kt * BK;
        const uint32_t dA = sA + s * A_STG * 2;
        #pragma unroll
        for (int it = 0; it < 4; it++) {
            int idx = it * 256 + tid;      // 0..1023
            int r = idx >> 3, u = idx & 7;
            cpa16(dA + (uint32_t)(r * 8 + (u ^ (r & 7))) * 16,
                  ga + (size_t)r * CK + u * 8);
        }
        const __half* gb = g_col + (((size_t)b * HW + n0) << 12) + (size_t)kt * BK;
        const uint32_t dB = sB + s * B_STG * 2;
        #pragma unroll
        for (int it = 0; it < 2; it++) {
            int idx = it * 256 + tid;      // 0..511
            int r = idx >> 3, u = idx & 7;
            cpa16(dB + (uint32_t)(r * 8 + (u ^ (r & 7))) * 16,
                  gb + ((size_t)r << 12) + u * 8);
        }
        CPA_COMMIT();
    };

    float acc[2][4][4];
    #pragma unroll
    for (int i = 0; i < 2; i++)
        #pragma unroll
        for (int n = 0; n < 4; n++)
            #pragma unroll
            for (int q = 0; q < 4; q++) acc[i][n][q] = 0.f;

    load_tile(0, 0);
    load_tile(1, 1);

    for (int kt = 0; kt < NT; kt++) {
        const int s = kt % NSTG;
        if (kt < NT - 1) asm volatile("cp.async.wait_group 1;" ::: "memory");
        else             asm volatile("cp.async.wait_group 0;" ::: "memory");
        __syncthreads();

        const uint32_t aBase = sA + s * A_STG * 2;
        const uint32_t bBase = sB + s * B_STG * 2;

        #pragma unroll
        for (int kk = 0; kk < 4; kk++) {
            uint32_t a[2][4];
            #pragma unroll
            for (int i = 0; i < 2; i++) {
                const int r = wm + i * 16 + (lane & 15);
                const int u = (kk * 2 + (lane >> 4)) ^ (r & 7);
                ldsm_x4(a[i][0], a[i][1], a[i][2], a[i][3],
                        aBase + (uint32_t)(r * 8 + u) * 16);
            }
            uint32_t bb[4][2];
            #pragma unroll
            for (int p = 0; p < 2; p++) {
                const int r = wn + p * 16 + (lane & 15);   // n row
                const int u = (kk * 2 + (lane >> 4)) ^ (r & 7);
                uint32_t r0, r1, r2, r3;
                ldsm_x4(r0, r1, r2, r3, bBase + (uint32_t)(r * 8 + u) * 16);
                bb[2 * p][0] = r0;     bb[2 * p][1] = r2;
                bb[2 * p + 1][0] = r1; bb[2 * p + 1][1] = r3;
            }
            #pragma unroll
            for (int i = 0; i < 2; i++)
                #pragma unroll
                for (int n = 0; n < 4; n++)
                    mma16816(acc[i][n], a[i], bb[n]);
        }

        if (kt + 2 < NT) load_tile(kt + 2, (kt + 2) % NSTG);
    }

    // ---- Epilogue: write conv + fused GN partial stats --------------------
    #pragma unroll
    for (int i = 0; i < 2; i++) {
        const int ml = wm + i * 16 + (lane >> 2);
        float* row0 = g_conv + ((size_t)b * C + my * BM + ml) * HW + n0 + wn;
        float* row1 = row0 + (size_t)8 * HW;
        #pragma unroll
        for (int n = 0; n < 4; n++) {
            const int col = n * 8 + (lane & 3) * 2;
            *(float2*)(row0 + col) = make_float2(acc[i][n][0], acc[i][n][1]);
            *(float2*)(row1 + col) = make_float2(acc[i][n][2], acc[i][n][3]);
        }
    }

    __syncthreads();
    float* part = (float*)sm;              // [16 local groups][sum,ss]
    if (tid < 32) part[tid] = 0.f;
    __syncthreads();

    #pragma unroll
    for (int i = 0; i < 2; i++) {
        float s0 = 0.f, q0 = 0.f, s1 = 0.f, q1 = 0.f;
        #pragma unroll
        for (int n = 0; n < 4; n++) {
            s0 += acc[i][n][0] + acc[i][n][1];
            q0 += acc[i][n][0] * acc[i][n][0] + acc[i][n][1] * acc[i][n][1];
            s1 += acc[i][n][2] + acc[i][n][3];
            q1 += acc[i][n][2] * acc[i][n][2] + acc[i][n][3] * acc[i][n][3];
        }
        #pragma unroll
        for (int o = 1; o < 4; o <<= 1) {
            s0 += __shfl_xor_sync(0xffffffff, s0, o);
            q0 += __shfl_xor_sync(0xffffffff, q0, o);
            s1 += __shfl_xor_sync(0xffffffff, s1, o);
            q1 += __shfl_xor_sync(0xffffffff, q1, o);
        }
        if ((lane & 3) == 0) {
            const int ml = wm + i * 16 + (lane >> 2);
            atomicAdd(&part[(ml >> 3) * 2],           s0);
            atomicAdd(&part[(ml >> 3) * 2 + 1],       q0);
            atomicAdd(&part[((ml + 8) >> 3) * 2],     s1);
            atomicAdd(&part[((ml + 8) >> 3) * 2 + 1], q1);
        }
    }
    __syncthreads();
    if (tid < 16) {
        atomicAdd(&g_gsum[b * GN + my * 16 + tid], part[tid * 2]);
        atomicAdd(&g_gss[b * GN + my * 16 + tid],  part[tid * 2 + 1]);
    }
}

// ---------------------------------------------------------------------------
// Kernel 3: normalize + affine + ReLU (stats finalized inline)
// ---------------------------------------------------------------------------
__global__ void gn_norm_kernel(const float* __restrict__ gamma,
                               const float* __restrict__ beta,
                               float* __restrict__ out)
{
    const size_t base = (size_t)blockIdx.x * 1024;
    const int c  = (int)((base >> 12) & 255);
    const int b  = (int)(base >> 20);
    const int gi = b * GN + (c >> 3);

    const float inv_n = 1.f / (float)(CPG * HW);
    const float mu  = g_gsum[gi] * inv_n;
    const float var = g_gss[gi] * inv_n - mu * mu;
    const float rs  = rsqrtf(var + 1e-5f);
    const float ga  = gamma[c] * rs;
    const float be  = beta[c] - mu * ga;

    const size_t i = base + threadIdx.x * 4;
    float4 v = *(const float4*)(g_conv + i);
    v.x = fmaxf(v.x * ga + be, 0.f);
    v.y = fmaxf(v.y * ga + be, 0.f);
    v.z = fmaxf(v.z * ga + be, 0.f);
    v.w = fmaxf(v.w * ga + be, 0.f);
    *(float4*)(out + i) = v;
}

// ---------------------------------------------------------------------------
extern "C" void kernel_launch(void* const* d_in, const int* in_sizes, int n_in,
                              void* d_out, int out_size)
{
    const float* x        = (const float*)d_in[0];
    const float* shp      = (const float*)d_in[1];
    const float* w_offset = (const float*)d_in[2];
    const float* w_deform = (const float*)d_in[3];
    const float* gamma    = (const float*)d_in[4];
    const float* beta     = (const float*)d_in[5];
    float* out = (float*)d_out;

    static bool attr_set = false;
    if (!attr_set) {
        cudaFuncSetAttribute(gemm_kernel, cudaFuncAttributeMaxDynamicSharedMemorySize,
                             GEMM_SMEM);
        attr_set = true;
    }

    prep_kernel<<<8768, 256>>>(x, w_deform);

    dim3 g1(HW / 512, DG * K2, B);         // (8, 36, 8)
    im2col_kernel<<<g1, 256>>>(shp, w_offset);

    dim3 g2(HW / BN, C / BM, B);           // (64, 2, 8)
    gemm_kernel<<<g2, 256, GEMM_SMEM>>>();

    gn_norm_kernel<<<(unsigned)((size_t)B * C * HW / 1024), 256>>>(gamma, beta, out);
}

// round 16
// speedup vs baseline: 1.0844x; 1.0327x over previous
#include <cuda_runtime.h>
#include <cuda_fp16.h>
#include <cstdint>

// Problem constants
constexpr int B  = 8;
constexpr int C  = 256;
constexpr int H  = 64;
constexpr int W  = 64;
constexpr int HW = H * W;          // 4096
constexpr int K2 = 9;
constexpr int DG = 4;
constexpr int CG = C / DG;         // 64
constexpr int CK = C * K2;         // 2304  (K order: ck' = (g*9+k)*64 + ci)
constexpr int CKP = 4096;          // padded col row stride (power of 2)
constexpr int GN = 32;
constexpr int CPG = C / GN;        // 8

// Scratch (static device arrays)
__device__ __align__(16) __half g_col[(size_t)B * HW * CKP];  // 268 MB col[b][p][ck'] (padded)
__device__ __align__(16) __half g_A[(size_t)C * CK];          // fp16 weights [m][ck']
__device__ __align__(16) float  g_xt[(size_t)B * HW * C];     // 33.5 MB x_t[b][p][c]
__device__ float g_conv[(size_t)B * C * HW];                  // 33.5 MB conv output
__device__ float g_gsum[B * GN];
__device__ float g_gss[B * GN];

// ---------------------------------------------------------------------------
// PTX helpers (baseline PTX only — toolchain targets compute_103, no tcgen05)
// ---------------------------------------------------------------------------
__device__ __forceinline__ uint32_t smem_u32(const void* p) {
    uint32_t a;
    asm("{ .reg .u64 t; cvta.to.shared.u64 t, %1; cvt.u32.u64 %0, t; }" : "=r"(a) : "l"(p));
    return a;
}
__device__ __forceinline__ void cpa16(uint32_t s, const void* g) {
    asm volatile("cp.async.cg.shared.global [%0], [%1], 16;" :: "r"(s), "l"(g));
}
#define CPA_COMMIT() asm volatile("cp.async.commit_group;" ::: "memory")

__device__ __forceinline__ void ldsm_x4(uint32_t& r0, uint32_t& r1, uint32_t& r2,
                                        uint32_t& r3, uint32_t addr) {
    asm volatile("ldmatrix.sync.aligned.m8n8.x4.shared.b16 {%0,%1,%2,%3}, [%4];"
                 : "=r"(r0), "=r"(r1), "=r"(r2), "=r"(r3) : "r"(addr));
}
__device__ __forceinline__ void mma16816(float* c, const uint32_t* a, const uint32_t* b) {
    asm volatile(
        "mma.sync.aligned.m16n8k16.row.col.f32.f16.f16.f32 "
        "{%0,%1,%2,%3}, {%4,%5,%6,%7}, {%8,%9}, {%0,%1,%2,%3};"
        : "+f"(c[0]), "+f"(c[1]), "+f"(c[2]), "+f"(c[3])
        : "r"(a[0]), "r"(a[1]), "r"(a[2]), "r"(a[3]), "r"(b[0]), "r"(b[1]));
}

// 4-channel bilinear gather from transposed image (base = x_t[b][.][c0])
__device__ __forceinline__ float4 bilinear4(const float* __restrict__ base,
                                            float py, float px) {
    const float y0f = floorf(py);
    const float x0f = floorf(px);
    const float ly = py - y0f;
    const float lx = px - x0f;
    const int iy0 = (int)y0f, ix0 = (int)x0f;
    const int iy1 = iy0 + 1,  ix1 = ix0 + 1;

    const bool vy0 = (iy0 >= 0) && (iy0 <= H - 1);
    const bool vy1 = (iy1 >= 0) && (iy1 <= H - 1);
    const bool vx0 = (ix0 >= 0) && (ix0 <= W - 1);
    const bool vx1 = (ix1 >= 0) && (ix1 <= W - 1);

    const int yc0 = min(max(iy0, 0), H - 1);
    const int yc1 = min(max(iy1, 0), H - 1);
    const int xc0 = min(max(ix0, 0), W - 1);
    const int xc1 = min(max(ix1, 0), W - 1);

    const float w00 = (1.f - ly) * (1.f - lx) * ((vy0 && vx0) ? 1.f : 0.f);
    const float w01 = (1.f - ly) * lx         * ((vy0 && vx1) ? 1.f : 0.f);
    const float w10 = ly * (1.f - lx)         * ((vy1 && vx0) ? 1.f : 0.f);
    const float w11 = ly * lx                 * ((vy1 && vx1) ? 1.f : 0.f);

    const float4 t00 = *(const float4*)(base + (size_t)(yc0 * W + xc0) * C);
    const float4 t01 = *(const float4*)(base + (size_t)(yc0 * W + xc1) * C);
    const float4 t10 = *(const float4*)(base + (size_t)(yc1 * W + xc0) * C);
    const float4 t11 = *(const float4*)(base + (size_t)(yc1 * W + xc1) * C);

    float4 r;
    r.x = w00 * t00.x + w01 * t01.x + w10 * t10.x + w11 * t11.x;
    r.y = w00 * t00.y + w01 * t01.y + w10 * t10.y + w11 * t11.y;
    r.z = w00 * t00.z + w01 * t01.z + w10 * t10.z + w11 * t11.z;
    r.w = w00 * t00.w + w01 * t01.w + w10 * t10.w + w11 * t11.w;
    return r;
}

// ---------------------------------------------------------------------------
// Kernel 0 (merged prep): transpose x -> x_t  AND  weight convert + stat zero
// ---------------------------------------------------------------------------
__global__ void __launch_bounds__(256) prep_kernel(const float* __restrict__ x,
                                                   const float* __restrict__ w)
{
    const int bid = blockIdx.x;
    const int tid = threadIdx.x;

    if (bid < 8192) {
        __shared__ float t[32][33];
        const int b  = bid >> 10;
        const int cB = ((bid >> 7) & 7) * 32;
        const int pB = (bid & 127) * 32;
        const int tx = tid & 31, ty = tid >> 5;   // (32, 8)

        const float* xb = x + (size_t)b * C * HW;
        #pragma unroll
        for (int j = 0; j < 4; j++)
            t[ty + j * 8][tx] = xb[(size_t)(cB + ty + j * 8) * HW + pB + tx];
        __syncthreads();
        float* xtb = g_xt + (size_t)b * HW * C;
        #pragma unroll
        for (int j = 0; j < 4; j++)
            xtb[(size_t)(pB + ty + j * 8) * C + cB + tx] = t[tx][ty + j * 8];
    } else {
        const int bid2 = bid - 8192;              // 0..575
        const int i0 = bid2 * 1024 + tid * 4;     // C*CK = 576*1024 exactly
        const int m   = i0 / CK;
        const int ckp = i0 % CK;
        const int gk  = ckp >> 6;
        const int ci  = ckp & 63;
        const int g   = gk / 9;
        const int k   = gk % 9;
        const float* wp = w + ((size_t)m * C + g * CG + ci) * K2 + k;
        __half hv[4];
        #pragma unroll
        for (int q = 0; q < 4; q++)
            hv[q] = __float2half(wp[(size_t)q * K2]);
        *(uint2*)(g_A + i0) = *(uint2*)hv;

        if (bid2 == 0 && tid < B * GN) {
            g_gsum[tid] = 0.f;
            g_gss[tid]  = 0.f;
        }
    }
}

// ---------------------------------------------------------------------------
// Kernel 1: im2col — dense gather, 8 position-pairs per thread (measured opt)
// col[b][p][gk*64+ci] with row stride CKP=4096.  Grid: (HW/256=16, 36, B)
// ---------------------------------------------------------------------------
__global__ void __launch_bounds__(256) im2col_kernel(
    const float* __restrict__ shp, const float* __restrict__ w_offset)
{
    const int tid = threadIdx.x;
    const int gk  = blockIdx.y;
    const int b   = blockIdx.z;
    const int g   = gk / 9, k = gk % 9;

    const float fki = (float)(k / 3 - 1);
    const float fkj = (float)(k % 3 - 1);

    const int ci4 = (tid & 15) * 4;
    const int t16 = tid >> 4;                 // 0..15
    const float* base = g_xt + (size_t)b * HW * C + g * CG + ci4;
    const float* wo = w_offset + (size_t)gk * 8;
    const float wo0 = wo[0], wo1 = wo[1], wo2 = wo[2], wo3 = wo[3];
    const float wo4 = wo[4], wo5 = wo[5], wo6 = wo[6], wo7 = wo[7];

    const int pblk = blockIdx.x * 256;

    #pragma unroll
    for (int pi = 0; pi < 8; pi++) {
        const int pair = pi * 16 + t16;       // 0..127
        const int pl   = pair * 2;
        const int p0   = pblk + pl;
        const int h    = p0 >> 6;
        const int w0   = p0 & 63;

        const float* sp = shp + (size_t)b * 4 * HW + p0;
        const float2 sA2 = *(const float2*)(sp);
        const float2 sB2 = *(const float2*)(sp + HW);
        const float2 sC2 = *(const float2*)(sp + 2 * HW);
        const float2 sD2 = *(const float2*)(sp + 3 * HW);

        const float dy0 = wo0 * sA2.x + wo1 * sB2.x + wo2 * sC2.x + wo3 * sD2.x;
        const float dy1 = wo0 * sA2.y + wo1 * sB2.y + wo2 * sC2.y + wo3 * sD2.y;
        const float dx0 = wo4 * sA2.x + wo5 * sB2.x + wo6 * sC2.x + wo7 * sD2.x;
        const float dx1 = wo4 * sA2.y + wo5 * sB2.y + wo6 * sC2.y + wo7 * sD2.y;

        const float4 v0 = bilinear4(base, dy0 + fki + h, dx0 + fkj + w0);
        const float4 v1 = bilinear4(base, dy1 + fki + h, dx1 + fkj + w0 + 1.f);

        __half* c0 = g_col + (((size_t)b * HW + p0) << 12) + gk * 64 + ci4;
        {
            __half2 t2[2] = { __floats2half2_rn(v0.x, v0.y),
                              __floats2half2_rn(v0.z, v0.w) };
            *(uint2*)c0 = *(uint2*)t2;
        }
        __half* c1 = c0 + CKP;
        {
            __half2 t2[2] = { __floats2half2_rn(v1.x, v1.y),
                              __floats2half2_rn(v1.z, v1.w) };
            *(uint2*)c1 = *(uint2*)t2;
        }
    }
}

// ---------------------------------------------------------------------------
// Kernel 2: HMMA GEMM + fused GN partial statistics  (round-13 base + two
// latency tweaks: prefetch-before-mma, my-adjacent grid for B L2 pairing)
// BM=128, BN=64, BK=64; 3-stage cp.async pipeline, XOR-swizzled smem,
// 3 CTAs/SM. A: [m][k] K-major. B: [n][k] n-major (non-trans ldsm, remap).
// Grid: (C/BM=2, HW/BN=64, B) — my pairs co-scheduled for B-tile L2 reuse.
// ---------------------------------------------------------------------------
constexpr int BM = 128, BN = 64, BK = 64;
constexpr int NT = CK / BK;               // 36
constexpr int NSTG = 3;
constexpr int A_STG = BM * BK;            // 16 KB
constexpr int B_STG = BN * BK;            // 8 KB
constexpr uint32_t GEMM_SMEM = NSTG * (A_STG + B_STG) * 2;  // 73728 B

__global__ void __launch_bounds__(256, 3) gemm_kernel()
{
    extern __shared__ __half sm[];
    const uint32_t sA = smem_u32(sm);
    const uint32_t sB = sA + NSTG * A_STG * 2;

    const int tid  = threadIdx.x;
    const int lane = tid & 31;
    const int warp = tid >> 5;
    const int my   = blockIdx.x;          // m-tile (0/1) — fastest: pairs adjacent
    const int n0   = blockIdx.y * BN;
    const int b    = blockIdx.z;
    const int wm   = (warp >> 1) * 32;
    const int wn   = (warp & 1) * 32;

    auto load_tile = [&](int kt, int s) {
        const __half* ga = g_A + ((size_t)my * BM) * CK + (size_t)kt * BK;
        const uint32_t dA = sA + s * A_STG * 2;
        #pragma unroll
        for (int it = 0; it < 4; it++) {
            int idx = it * 256 + tid;      // 0..1023
            int r = idx >> 3, u = idx & 7;
            cpa16(dA + (uint32_t)(r * 8 + (u ^ (r & 7))) * 16,
                  ga + (size_t)r * CK + u * 8);
        }
        const __half* gb = g_col + (((size_t)b * HW + n0) << 12) + (size_t)kt * BK;
        const uint32_t dB = sB + s * B_STG * 2;
        #pragma unroll
        for (int it = 0; it < 2; it++) {
            int idx = it * 256 + tid;      // 0..511
            int r = idx >> 3, u = idx & 7;
            cpa16(dB + (uint32_t)(r * 8 + (u ^ (r & 7))) * 16,
                  gb + ((size_t)r << 12) + u * 8);
        }
        CPA_COMMIT();
    };

    float acc[2][4][4];
    #pragma unroll
    for (int i = 0; i < 2; i++)
        #pragma unroll
        for (int n = 0; n < 4; n++)
            #pragma unroll
            for (int q = 0; q < 4; q++) acc[i][n][q] = 0.f;

    load_tile(0, 0);
    load_tile(1, 1);

    for (int kt = 0; kt < NT; kt++) {
        const int s = kt % NSTG;
        if (kt < NT - 1) asm volatile("cp.async.wait_group 1;" ::: "memory");
        else             asm volatile("cp.async.wait_group 0;" ::: "memory");
        __syncthreads();
        // Prefetch kt+2 into the stage all warps just released (barrier above
        // proves stage (kt+2)%3 == (kt-1)%3 is free) — overlaps the full mma block.
        if (kt + 2 < NT) load_tile(kt + 2, (kt + 2) % NSTG);

        const uint32_t aBase = sA + s * A_STG * 2;
        const uint32_t bBase = sB + s * B_STG * 2;

        #pragma unroll
        for (int kk = 0; kk < 4; kk++) {
            uint32_t a[2][4];
            #pragma unroll
            for (int i = 0; i < 2; i++) {
                const int r = wm + i * 16 + (lane & 15);
                const int u = (kk * 2 + (lane >> 4)) ^ (r & 7);
                ldsm_x4(a[i][0], a[i][1], a[i][2], a[i][3],
                        aBase + (uint32_t)(r * 8 + u) * 16);
            }
            uint32_t bb[4][2];
            #pragma unroll
            for (int p = 0; p < 2; p++) {
                const int r = wn + p * 16 + (lane & 15);   // n row
                const int u = (kk * 2 + (lane >> 4)) ^ (r & 7);
                uint32_t r0, r1, r2, r3;
                ldsm_x4(r0, r1, r2, r3, bBase + (uint32_t)(r * 8 + u) * 16);
                bb[2 * p][0] = r0;     bb[2 * p][1] = r2;
                bb[2 * p + 1][0] = r1; bb[2 * p + 1][1] = r3;
            }
            #pragma unroll
            for (int i = 0; i < 2; i++)
                #pragma unroll
                for (int n = 0; n < 4; n++)
                    mma16816(acc[i][n], a[i], bb[n]);
        }
    }

    // ---- Epilogue: write conv + fused GN partial stats --------------------
    #pragma unroll
    for (int i = 0; i < 2; i++) {
        const int ml = wm + i * 16 + (lane >> 2);
        float* row0 = g_conv + ((size_t)b * C + my * BM + ml) * HW + n0 + wn;
        float* row1 = row0 + (size_t)8 * HW;
        #pragma unroll
        for (int n = 0; n < 4; n++) {
            const int col = n * 8 + (lane & 3) * 2;
            *(float2*)(row0 + col) = make_float2(acc[i][n][0], acc[i][n][1]);
            *(float2*)(row1 + col) = make_float2(acc[i][n][2], acc[i][n][3]);
        }
    }

    __syncthreads();
    float* part = (float*)sm;              // [16 local groups][sum,ss]
    if (tid < 32) part[tid] = 0.f;
    __syncthreads();

    #pragma unroll
    for (int i = 0; i < 2; i++) {
        float s0 = 0.f, q0 = 0.f, s1 = 0.f, q1 = 0.f;
        #pragma unroll
        for (int n = 0; n < 4; n++) {
            s0 += acc[i][n][0] + acc[i][n][1];
            q0 += acc[i][n][0] * acc[i][n][0] + acc[i][n][1] * acc[i][n][1];
            s1 += acc[i][n][2] + acc[i][n][3];
            q1 += acc[i][n][2] * acc[i][n][2] + acc[i][n][3] * acc[i][n][3];
        }
        #pragma unroll
        for (int o = 1; o < 4; o <<= 1) {
            s0 += __shfl_xor_sync(0xffffffff, s0, o);
            q0 += __shfl_xor_sync(0xffffffff, q0, o);
            s1 += __shfl_xor_sync(0xffffffff, s1, o);
            q1 += __shfl_xor_sync(0xffffffff, q1, o);
        }
        if ((lane & 3) == 0) {
            const int ml = wm + i * 16 + (lane >> 2);
            atomicAdd(&part[(ml >> 3) * 2],           s0);
            atomicAdd(&part[(ml >> 3) * 2 + 1],       q0);
            atomicAdd(&part[((ml + 8) >> 3) * 2],     s1);
            atomicAdd(&part[((ml + 8) >> 3) * 2 + 1], q1);
        }
    }
    __syncthreads();
    if (tid < 16) {
        atomicAdd(&g_gsum[b * GN + my * 16 + tid], part[tid * 2]);
        atomicAdd(&g_gss[b * GN + my * 16 + tid],  part[tid * 2 + 1]);
    }
}

// ---------------------------------------------------------------------------
// Kernel 3: normalize + affine + ReLU (stats finalized inline)
// ---------------------------------------------------------------------------
__global__ void gn_norm_kernel(const float* __restrict__ gamma,
                               const float* __restrict__ beta,
                               float* __restrict__ out)
{
    const size_t base = (size_t)blockIdx.x * 1024;
    const int c  = (int)((base >> 12) & 255);
    const int b  = (int)(base >> 20);
    const int gi = b * GN + (c >> 3);

    const float inv_n = 1.f / (float)(CPG * HW);
    const float mu  = g_gsum[gi] * inv_n;
    const float var = g_gss[gi] * inv_n - mu * mu;
    const float rs  = rsqrtf(var + 1e-5f);
    const float ga  = gamma[c] * rs;
    const float be  = beta[c] - mu * ga;

    const size_t i = base + threadIdx.x * 4;
    float4 v = *(const float4*)(g_conv + i);
    v.x = fmaxf(v.x * ga + be, 0.f);
    v.y = fmaxf(v.y * ga + be, 0.f);
    v.z = fmaxf(v.z * ga + be, 0.f);
    v.w = fmaxf(v.w * ga + be, 0.f);
    *(float4*)(out + i) = v;
}

// ---------------------------------------------------------------------------
extern "C" void kernel_launch(void* const* d_in, const int* in_sizes, int n_in,
                              void* d_out, int out_size)
{
    const float* x        = (const float*)d_in[0];
    const float* shp      = (const float*)d_in[1];
    const float* w_offset = (const float*)d_in[2];
    const float* w_deform = (const float*)d_in[3];
    const float* gamma    = (const float*)d_in[4];
    const float* beta     = (const float*)d_in[5];
    float* out = (float*)d_out;

    static bool attr_set = false;
    if (!attr_set) {
        cudaFuncSetAttribute(gemm_kernel, cudaFuncAttributeMaxDynamicSharedMemorySize,
                             GEMM_SMEM);
        attr_set = true;
    }

    prep_kernel<<<8768, 256>>>(x, w_deform);

    dim3 g1(HW / 256, DG * K2, B);         // (16, 36, 8)
    im2col_kernel<<<g1, 256>>>(shp, w_offset);

    dim3 g2(C / BM, HW / BN, B);           // (2, 64, 8)
    gemm_kernel<<<g2, 256, GEMM_SMEM>>>();

    gn_norm_kernel<<<(unsigned)((size_t)B * C * HW / 1024), 256>>>(gamma, beta, out);
}